// round 4
// baseline (speedup 1.0000x reference)
#include <cuda_runtime.h>
#include <math.h>
#include <stdint.h>

// Problem constants (fixed by setup_inputs)
#define BS     8
#define HW     4096      // 64*64
#define VN     204       // hw // STEP
#define STEPV  20
#define PN     400
#define NPAIR  200       // PN/2 packed gt pairs
#define NT     160       // 5 warps
#define NITEMS (VN * BS) // 1632 work items
#define NBLK   592       // 148 SMs * 4 persistent blocks

// Scratch (no cudaMalloc allowed). Zero at load; last block resets for replay.
__device__ double       g_acc[2];      // [0]=loss sum, [1]=value sum
__device__ unsigned int g_count = 0;   // finished blocks
__device__ unsigned int g_work  = 0;   // work-item queue head

// Packed f32x2 FMA (Blackwell FFMA2 — only via PTX)
#define FMA2(d, a, b, c) \
    asm("fma.rn.f32x2 %0, %1, %2, %3;" : "=l"(d) : "l"(a), "l"(b), "l"(c))
#define UNPACK2(lo, hi, v) \
    asm("mov.b64 {%0, %1}, %2;" : "=r"(lo), "=r"(hi) : "l"(v))

__device__ __forceinline__ uint64_t pack2(float lo, float hi) {
    return (uint64_t)__float_as_uint(lo) | ((uint64_t)__float_as_uint(hi) << 32);
}

struct Rot { float R00,R01,R02,R10,R11,R12,R20,R21,R22,t0,t1,t2; };

// Heavy ADD-S inner: NC chains per warp. Chain id = wid + 5*k; points 32*chain+lane.
template<int NC>
__device__ __forceinline__ float adds_chains(
    const ulonglong2* __restrict__ sA, const ulonglong2* __restrict__ sB,
    const float* __restrict__ mb, const Rot& P, int wid, int lane)
{
    float pn_[NC], mlo[NC], mhi[NC];
    uint64_t ax[NC], ay[NC], az[NC];
    bool act[NC];
    #pragma unroll
    for (int k = 0; k < NC; k++) {
        const int chain = wid + 5 * k;
        const int p = 32 * chain + lane;
        act[k] = (p < PN);
        const int pp = act[k] ? p : (PN - 1);
        const float x = mb[pp], y = mb[PN + pp], z = mb[2*PN + pp];
        const float px = P.R00*x + P.R01*y + P.R02*z + P.t0;
        const float py = P.R10*x + P.R11*y + P.R12*z + P.t1;
        const float pz = P.R20*x + P.R21*y + P.R22*z + P.t2;
        pn_[k] = px*px + py*py + pz*pz;
        ax[k] = pack2(-2.0f*px, -2.0f*px);
        ay[k] = pack2(-2.0f*py, -2.0f*py);
        az[k] = pack2(-2.0f*pz, -2.0f*pz);
        mlo[k] = 3.4e38f; mhi[k] = 3.4e38f;
    }
    __syncthreads();   // staging (done by all warps before this call) visible

    #pragma unroll 2
    for (int j = 0; j < NPAIR; j++) {
        const ulonglong2 A = sA[j];   // (gx0,gx1),(gy0,gy1) — LDS.128 broadcast
        const ulonglong2 B = sB[j];   // (gz0,gz1),(gn0,gn1)
        #pragma unroll
        for (int k = 0; k < NC; k++) {
            uint64_t t;
            FMA2(t, az[k], B.x, B.y);
            FMA2(t, ay[k], A.y, t);
            FMA2(t, ax[k], A.x, t);
            uint32_t lo, hi;
            UNPACK2(lo, hi, t);
            mlo[k] = fminf(mlo[k], __uint_as_float(lo));
            mhi[k] = fminf(mhi[k], __uint_as_float(hi));
        }
    }
    float s = 0.0f;
    #pragma unroll
    for (int k = 0; k < NC; k++)
        if (act[k])
            s += sqrtf(fmaxf(pn_[k] + fminf(mlo[k], mhi[k]), 0.0f));
    return s;
}

__global__ __launch_bounds__(NT) void loss_kernel(
    const float* __restrict__ pred_r,     // (bs,4,h,w)
    const float* __restrict__ pred_t,     // (bs,3,h,w)
    const float* __restrict__ pred_score, // (bs,h,w)
    const float* __restrict__ gt_r,       // (bs,3,3)
    const float* __restrict__ gt_t,       // (bs,3)
    const int*   __restrict__ cls_ids,    // (bs,)
    const float* __restrict__ model,      // (bs,3,P)
    float* __restrict__ out)
{
    const int tid  = threadIdx.x;
    const int wid  = tid >> 5;
    const int lane = tid & 31;

    __shared__ ulonglong2   sA[NPAIR];
    __shared__ ulonglong2   sB[NPAIR];
    __shared__ float        red[NT / 32];
    __shared__ unsigned int s_item;

    double acc_loss = 0.0, acc_val = 0.0;   // tid0-local across items

    for (;;) {
        if (tid == 0) s_item = atomicAdd(&g_work, 1u);
        __syncthreads();
        const unsigned int my = s_item;
        if (my >= NITEMS) break;

        const int b = (int)(my & 7u);        // interleave batches in queue order
        const int v = (int)(my >> 3);
        const int c = cls_ids[b];
        const bool valid = (c >= 0 && c <= 29);
        const bool sym = (c == 12 || c == 15 || c == 18 || c == 19 || c == 20);

        float sum = 0.0f;
        float score = 0.0f;

        if (valid) {
            const int pix = v * STEPV;
            score = pred_score[(size_t)b * HW + pix];   // prefetch early

            // gt pose (broadcast, L2-resident)
            const float r00 = gt_r[b*9+0], r01 = gt_r[b*9+1], r02 = gt_r[b*9+2];
            const float r10 = gt_r[b*9+3], r11 = gt_r[b*9+4], r12 = gt_r[b*9+5];
            const float r20 = gt_r[b*9+6], r21 = gt_r[b*9+7], r22 = gt_r[b*9+8];
            const float t0g = gt_t[b*3+0], t1g = gt_t[b*3+1], t2g = gt_t[b*3+2];
            const float* mb = model + (size_t)b * 3 * PN;

            // Quaternion -> rotation (redundant per thread, cheap)
            const float* prb = pred_r + (size_t)b * 4 * HW;
            float q0 = prb[pix], q1 = prb[HW+pix], q2 = prb[2*HW+pix], q3 = prb[3*HW+pix];
            const float inv = rsqrtf(q0*q0 + q1*q1 + q2*q2 + q3*q3);
            q0 *= inv; q1 *= inv; q2 *= inv; q3 *= inv;
            Rot P;
            P.R00 = 1.0f - 2.0f*(q2*q2 + q3*q3);
            P.R01 = 2.0f*q1*q2 - 2.0f*q0*q3;
            P.R02 = 2.0f*q0*q2 + 2.0f*q1*q3;
            P.R10 = 2.0f*q1*q2 + 2.0f*q3*q0;
            P.R11 = 1.0f - 2.0f*(q1*q1 + q3*q3);
            P.R12 = -2.0f*q0*q1 + 2.0f*q2*q3;
            P.R20 = -2.0f*q0*q2 + 2.0f*q1*q3;
            P.R21 = 2.0f*q0*q1 + 2.0f*q2*q3;
            P.R22 = 1.0f - 2.0f*(q1*q1 + q2*q2);
            const float* ptb = pred_t + (size_t)b * 3 * HW;
            P.t0 = ptb[pix]; P.t1 = ptb[HW+pix]; P.t2 = ptb[2*HW+pix];

            if (!sym) {
                // ADD: direct, no staging/barriers
                for (int p = tid; p < PN; p += NT) {
                    const float x = mb[p], y = mb[PN + p], z = mb[2*PN + p];
                    const float dx = P.R00*x + P.R01*y + P.R02*z + P.t0 - (r00*x + r01*y + r02*z + t0g);
                    const float dy = P.R10*x + P.R11*y + P.R12*z + P.t1 - (r10*x + r11*y + r12*z + t1g);
                    const float dz = P.R20*x + P.R21*y + P.R22*z + P.t2 - (r20*x + r21*y + r22*z + t2g);
                    sum += sqrtf(dx*dx + dy*dy + dz*dz);
                }
            } else {
                // Stage packed gt pairs (pair j = points 2j, 2j+1)
                for (int j = tid; j < NPAIR; j += NT) {
                    const float x0 = mb[2*j],   y0 = mb[PN+2*j],   z0 = mb[2*PN+2*j];
                    const float x1 = mb[2*j+1], y1 = mb[PN+2*j+1], z1 = mb[2*PN+2*j+1];
                    const float gx0 = r00*x0 + r01*y0 + r02*z0 + t0g;
                    const float gy0 = r10*x0 + r11*y0 + r12*z0 + t1g;
                    const float gz0 = r20*x0 + r21*y0 + r22*z0 + t2g;
                    const float gx1 = r00*x1 + r01*y1 + r02*z1 + t0g;
                    const float gy1 = r10*x1 + r11*y1 + r12*z1 + t1g;
                    const float gz1 = r20*x1 + r21*y1 + r22*z1 + t2g;
                    sA[j] = make_ulonglong2(pack2(gx0,gx1), pack2(gy0,gy1));
                    sB[j] = make_ulonglong2(pack2(gz0,gz1),
                                            pack2(gx0*gx0+gy0*gy0+gz0*gz0,
                                                  gx1*gx1+gy1*gy1+gz1*gz1));
                }
                // 13 warp-chains over 5 warps: warps 0-2 take 3 chains, 3-4 take 2.
                if (wid < 3) sum = adds_chains<3>(sA, sB, mb, P, wid, lane);
                else         sum = adds_chains<2>(sA, sB, mb, P, wid, lane);
            }
        }

        // Block reduction (uniform)
        #pragma unroll
        for (int off = 16; off > 0; off >>= 1)
            sum += __shfl_down_sync(0xFFFFFFFFu, sum, off);
        if (lane == 0) red[wid] = sum;
        __syncthreads();

        if (tid == 0 && valid) {
            float tot = red[0];
            #pragma unroll
            for (int w = 1; w < NT/32; w++) tot += red[w];
            const float add_ij = tot / (float)PN;
            acc_loss += (double)(add_ij * score - 0.01f * logf(score));
            acc_val  += (double)add_ij;
        }
        __syncthreads();   // red[] reuse + sA/sB restage safety
    }

    // One atomic pair per block, then last block finalizes.
    if (tid == 0) {
        const double scale = 1.0 / ((double)VN * (double)BS);
        atomicAdd(&g_acc[0], acc_loss * scale);
        atomicAdd(&g_acc[1], acc_val  * scale);
        __threadfence();
        const unsigned int old = atomicAdd(&g_count, 1u);
        if (old == (unsigned int)(NBLK - 1)) {
            __threadfence();
            const double gl = *(volatile double*)&g_acc[0];
            const double gv = *(volatile double*)&g_acc[1];
            float glf = (float)gl;
            const float gvf = (float)gv;
            if (isinf(glf) || isnan(glf)) glf = 0.0f;
            out[0] = glf + 0.0f * gvf;   // faithful to reference
            g_acc[0] = 0.0;
            g_acc[1] = 0.0;
            g_count  = 0u;
            g_work   = 0u;               // reset queue for next graph replay
        }
    }
}

extern "C" void kernel_launch(void* const* d_in, const int* in_sizes, int n_in,
                              void* d_out, int out_size) {
    const float* pred_r     = (const float*)d_in[0];
    const float* pred_t     = (const float*)d_in[1];
    const float* pred_score = (const float*)d_in[2];
    const float* gt_r       = (const float*)d_in[3];
    const float* gt_t       = (const float*)d_in[4];
    const int*   cls_ids    = (const int*)  d_in[5];
    const float* model_xyz  = (const float*)d_in[6];
    float* out = (float*)d_out;

    loss_kernel<<<NBLK, NT>>>(pred_r, pred_t, pred_score, gt_r, gt_t,
                              cls_ids, model_xyz, out);
}

// round 5
// speedup vs baseline: 1.0585x; 1.0585x over previous
#include <cuda_runtime.h>
#include <math.h>
#include <stdint.h>

// Problem constants (fixed by setup_inputs)
#define BS     8
#define HW     4096      // 64*64
#define VN     204       // hw // STEP
#define STEPV  20
#define PN     400
#define NPAIR  200       // PN/2 packed gt pairs
#define NT     128       // 4 warps, 1 per SMSP
#define NBLK   592       // 148 SMs * 4
#define SPLIT  4         // pred-point chunks per heavy view
#define HPB    (VN*SPLIT) // 816 heavy split-items per sym batch

// Scratch (no cudaMalloc). Zero at load; last block resets for graph replay.
__device__ double       g_acc[2];     // [0]=loss sum, [1]=value sum
__device__ unsigned int g_count = 0;

// Packed f32x2 FMA (Blackwell FFMA2 — only via PTX)
#define FMA2(d, a, b, c) \
    asm("fma.rn.f32x2 %0, %1, %2, %3;" : "=l"(d) : "l"(a), "l"(b), "l"(c))
#define UNPACK2(lo, hi, v) \
    asm("mov.b64 {%0, %1}, %2;" : "=r"(lo), "=r"(hi) : "l"(v))

__device__ __forceinline__ uint64_t pack2(float lo, float hi) {
    return (uint64_t)__float_as_uint(lo) | ((uint64_t)__float_as_uint(hi) << 32);
}

// Quaternion at pixel -> rotation+translation (registers; redundant per thread)
struct Pose { float R00,R01,R02,R10,R11,R12,R20,R21,R22,t0,t1,t2; };

__device__ __forceinline__ Pose pred_pose(const float* __restrict__ pred_r,
                                          const float* __restrict__ pred_t,
                                          int b, int pix)
{
    const float* prb = pred_r + (size_t)b * 4 * HW;
    float q0 = prb[pix], q1 = prb[HW+pix], q2 = prb[2*HW+pix], q3 = prb[3*HW+pix];
    const float inv = rsqrtf(q0*q0 + q1*q1 + q2*q2 + q3*q3);
    q0 *= inv; q1 *= inv; q2 *= inv; q3 *= inv;
    Pose P;
    P.R00 = 1.0f - 2.0f*(q2*q2 + q3*q3);
    P.R01 = 2.0f*q1*q2 - 2.0f*q0*q3;
    P.R02 = 2.0f*q0*q2 + 2.0f*q1*q3;
    P.R10 = 2.0f*q1*q2 + 2.0f*q3*q0;
    P.R11 = 1.0f - 2.0f*(q1*q1 + q3*q3);
    P.R12 = -2.0f*q0*q1 + 2.0f*q2*q3;
    P.R20 = -2.0f*q0*q2 + 2.0f*q1*q3;
    P.R21 = 2.0f*q0*q1 + 2.0f*q2*q3;
    P.R22 = 1.0f - 2.0f*(q1*q1 + q2*q2);
    const float* ptb = pred_t + (size_t)b * 3 * HW;
    P.t0 = ptb[pix]; P.t1 = ptb[HW+pix]; P.t2 = ptb[2*HW+pix];
    return P;
}

__global__ __launch_bounds__(NT) void loss_kernel(
    const float* __restrict__ pred_r,     // (bs,4,h,w)
    const float* __restrict__ pred_t,     // (bs,3,h,w)
    const float* __restrict__ pred_score, // (bs,h,w)
    const float* __restrict__ gt_r,       // (bs,3,3)
    const float* __restrict__ gt_t,       // (bs,3)
    const int*   __restrict__ cls_ids,    // (bs,)
    const float* __restrict__ model,      // (bs,3,P)
    float* __restrict__ out)
{
    const int tid  = threadIdx.x;
    const int wid  = tid >> 5;
    const int lane = tid & 31;
    const int bid  = blockIdx.x;

    __shared__ ulonglong2 sA[NPAIR];   // (gx0,gx1),(gy0,gy1)
    __shared__ ulonglong2 sB[NPAIR];   // (gz0,gz1),(gn0,gn1)
    __shared__ float      redf[4];
    __shared__ double     redd[8];

    // Classify batches (8 broadcast LDGs; registers only)
    unsigned sym_mask = 0u, light_mask = 0u;
    #pragma unroll
    for (int b = 0; b < BS; b++) {
        const int c = cls_ids[b];
        const bool val = (c >= 0 && c <= 29);
        const bool sy  = (c==12 || c==15 || c==18 || c==19 || c==20);
        if (val &&  sy) sym_mask   |= (1u << b);
        if (val && !sy) light_mask |= (1u << b);
    }
    const int ns = __popc(sym_mask);
    const int nl = __popc(light_mask);

    double hL = 0.0, hV = 0.0;   // tid0-local heavy accumulators

    // ================= Heavy phase: ADD-S split-items, block-cooperative ====
    const int H = HPB * ns;
    int cached_b = -1;
    for (int h = bid; h < H; h += NBLK) {
        const int b_idx = h / HPB;
        const int rem   = h - b_idx * HPB;
        const int v     = rem >> 2;
        const int s     = rem & 3;
        const int b     = __fns(sym_mask, 0, b_idx + 1);

        const float* mb = model + (size_t)b * 3 * PN;

        if (b != cached_b) {
            // Stage packed gt pairs for this batch (pair j = points 2j,2j+1)
            const float r00 = gt_r[b*9+0], r01 = gt_r[b*9+1], r02 = gt_r[b*9+2];
            const float r10 = gt_r[b*9+3], r11 = gt_r[b*9+4], r12 = gt_r[b*9+5];
            const float r20 = gt_r[b*9+6], r21 = gt_r[b*9+7], r22 = gt_r[b*9+8];
            const float t0g = gt_t[b*3+0], t1g = gt_t[b*3+1], t2g = gt_t[b*3+2];
            for (int j = tid; j < NPAIR; j += NT) {
                const float x0 = mb[2*j],   y0 = mb[PN+2*j],   z0 = mb[2*PN+2*j];
                const float x1 = mb[2*j+1], y1 = mb[PN+2*j+1], z1 = mb[2*PN+2*j+1];
                const float gx0 = r00*x0 + r01*y0 + r02*z0 + t0g;
                const float gy0 = r10*x0 + r11*y0 + r12*z0 + t1g;
                const float gz0 = r20*x0 + r21*y0 + r22*z0 + t2g;
                const float gx1 = r00*x1 + r01*y1 + r02*z1 + t0g;
                const float gy1 = r10*x1 + r11*y1 + r12*z1 + t1g;
                const float gz1 = r20*x1 + r21*y1 + r22*z1 + t2g;
                sA[j] = make_ulonglong2(pack2(gx0,gx1), pack2(gy0,gy1));
                sB[j] = make_ulonglong2(pack2(gz0,gz1),
                                        pack2(gx0*gx0+gy0*gy0+gz0*gz0,
                                              gx1*gx1+gy1*gy1+gz1*gz1));
            }
            cached_b = b;
            __syncthreads();
        }

        const int pix = v * STEPV;
        const Pose P = pred_pose(pred_r, pred_t, b, pix);

        // One chain per warp: 25 pred points each, chunk s covers [100s,100s+100)
        const bool act = (lane < 25);
        const int  p   = 100*s + 25*wid + (act ? lane : 24);
        const float x = mb[p], y = mb[PN+p], z = mb[2*PN+p];
        const float px = P.R00*x + P.R01*y + P.R02*z + P.t0;
        const float py = P.R10*x + P.R11*y + P.R12*z + P.t1;
        const float pz = P.R20*x + P.R21*y + P.R22*z + P.t2;
        const float pn = px*px + py*py + pz*pz;
        const uint64_t ax = pack2(-2.0f*px, -2.0f*px);
        const uint64_t ay = pack2(-2.0f*py, -2.0f*py);
        const uint64_t az = pack2(-2.0f*pz, -2.0f*pz);

        float mlo = 3.4e38f, mhi = 3.4e38f;
        #pragma unroll 4
        for (int j = 0; j < NPAIR; j++) {
            const ulonglong2 A = sA[j];   // LDS.128 broadcast
            const ulonglong2 B = sB[j];
            uint64_t t;
            FMA2(t, az, B.x, B.y);
            FMA2(t, ay, A.y, t);
            FMA2(t, ax, A.x, t);
            uint32_t lo, hi;
            UNPACK2(lo, hi, t);
            mlo = fminf(mlo, __uint_as_float(lo));
            mhi = fminf(mhi, __uint_as_float(hi));
        }
        float sum = act ? sqrtf(fmaxf(pn + fminf(mlo, mhi), 0.0f)) : 0.0f;

        #pragma unroll
        for (int off = 16; off > 0; off >>= 1)
            sum += __shfl_down_sync(0xFFFFFFFFu, sum, off);
        if (lane == 0) redf[wid] = sum;
        __syncthreads();

        if (tid == 0) {
            const float add_part = (redf[0]+redf[1]+redf[2]+redf[3]) / (float)PN;
            const float sc = pred_score[(size_t)b * HW + pix];
            double lc = (double)(add_part * sc);
            if (s == 0) lc += (double)(-0.01f * logf(sc));  // log term once/view
            hL += lc;
            hV += (double)add_part;
        }
        __syncthreads();   // redf reuse + sA/sB restage safety
    }

    // ================= Light phase: ADD, one item per WARP (no barriers) ====
    double lLw = 0.0, lVw = 0.0;   // lane0-local per-warp accumulators
    const int L = VN * nl;
    for (int l = bid * 4 + wid; l < L; l += NBLK * 4) {
        const int b_idx = l / VN;
        const int v     = l - b_idx * VN;
        const int b     = __fns(light_mask, 0, b_idx + 1);

        const float r00 = gt_r[b*9+0], r01 = gt_r[b*9+1], r02 = gt_r[b*9+2];
        const float r10 = gt_r[b*9+3], r11 = gt_r[b*9+4], r12 = gt_r[b*9+5];
        const float r20 = gt_r[b*9+6], r21 = gt_r[b*9+7], r22 = gt_r[b*9+8];
        const float t0g = gt_t[b*3+0], t1g = gt_t[b*3+1], t2g = gt_t[b*3+2];
        const float* mb = model + (size_t)b * 3 * PN;

        const int pix = v * STEPV;
        const Pose P = pred_pose(pred_r, pred_t, b, pix);

        float sum = 0.0f;
        for (int p = lane; p < PN; p += 32) {
            const float x = mb[p], y = mb[PN+p], z = mb[2*PN+p];
            const float dx = P.R00*x + P.R01*y + P.R02*z + P.t0 - (r00*x + r01*y + r02*z + t0g);
            const float dy = P.R10*x + P.R11*y + P.R12*z + P.t1 - (r10*x + r11*y + r12*z + t1g);
            const float dz = P.R20*x + P.R21*y + P.R22*z + P.t2 - (r20*x + r21*y + r22*z + t2g);
            sum += sqrtf(dx*dx + dy*dy + dz*dz);
        }
        #pragma unroll
        for (int off = 16; off > 0; off >>= 1)
            sum += __shfl_down_sync(0xFFFFFFFFu, sum, off);
        if (lane == 0) {
            const float add_ij = sum / (float)PN;
            const float sc = pred_score[(size_t)b * HW + pix];
            lLw += (double)(add_ij * sc - 0.01f * logf(sc));
            lVw += (double)add_ij;
        }
    }

    // ================= Combine + single atomic pair per block ===============
    if (lane == 0) { redd[wid*2] = lLw; redd[wid*2+1] = lVw; }
    __syncthreads();

    if (tid == 0) {
        double Lacc = hL, Vacc = hV;
        #pragma unroll
        for (int w = 0; w < 4; w++) { Lacc += redd[w*2]; Vacc += redd[w*2+1]; }
        const double scale = 1.0 / ((double)VN * (double)BS);
        atomicAdd(&g_acc[0], Lacc * scale);
        atomicAdd(&g_acc[1], Vacc * scale);
        __threadfence();
        const unsigned int old = atomicAdd(&g_count, 1u);
        if (old == (unsigned int)(NBLK - 1)) {
            __threadfence();
            const double gl = *(volatile double*)&g_acc[0];
            const double gv = *(volatile double*)&g_acc[1];
            float glf = (float)gl;
            const float gvf = (float)gv;
            if (isinf(glf) || isnan(glf)) glf = 0.0f;
            out[0] = glf + 0.0f * gvf;   // faithful to reference
            g_acc[0] = 0.0;
            g_acc[1] = 0.0;
            g_count  = 0u;
        }
    }
}

extern "C" void kernel_launch(void* const* d_in, const int* in_sizes, int n_in,
                              void* d_out, int out_size) {
    const float* pred_r     = (const float*)d_in[0];
    const float* pred_t     = (const float*)d_in[1];
    const float* pred_score = (const float*)d_in[2];
    const float* gt_r       = (const float*)d_in[3];
    const float* gt_t       = (const float*)d_in[4];
    const int*   cls_ids    = (const int*)  d_in[5];
    const float* model_xyz  = (const float*)d_in[6];
    float* out = (float*)d_out;

    loss_kernel<<<NBLK, NT>>>(pred_r, pred_t, pred_score, gt_r, gt_t,
                              cls_ids, model_xyz, out);
}